// round 16
// baseline (speedup 1.0000x reference)
#include <cuda_runtime.h>
#include <cuda_bf16.h>
#include <cstdint>

#define BB 4
#define SS 2048
#define FF 1024
#define HH 16
#define DD 64

// ---------------------------------------------------------------------------
// Scratch (allocation-free requirement -> __device__ globals)
// ---------------------------------------------------------------------------
__device__ uint16_t g_wq_h[1048576], g_wq_l[1048576];
__device__ uint16_t g_wk_h[1048576], g_wk_l[1048576];
__device__ uint16_t g_wv_h[1048576], g_wv_l[1048576];
__device__ uint16_t g_fcw_h[1048576], g_fcw_l[1048576];
__device__ uint16_t g_qh_h[8388608], g_qh_l[8388608];   // [B,H,S,D]
__device__ uint16_t g_kh_h[8388608], g_kh_l[8388608];   // [B,H,S,D]
__device__ uint16_t g_vt_h[8388608], g_vt_l[8388608];   // [B,H,D,S]
__device__ uint16_t g_ctx_h[8388608], g_ctx_l[8388608]; // [B,S,F]
__device__ float    g_part[BB*HH*SS*16];                // per-(row, ntile) exp sums

// ---------------------------------------------------------------------------
__device__ __forceinline__ uint32_t smem_u32(const void* p) {
    uint32_t a;
    asm("{ .reg .u64 t; cvta.to.shared.u64 t, %1; cvt.u32.u64 %0, t; }"
        : "=r"(a) : "l"(p));
    return a;
}

__device__ __forceinline__ void ldsm4(uint32_t* r, uint32_t addr) {
    asm volatile("ldmatrix.sync.aligned.m8n8.x4.shared.b16 {%0,%1,%2,%3}, [%4];"
                 : "=r"(r[0]), "=r"(r[1]), "=r"(r[2]), "=r"(r[3]) : "r"(addr));
}

__device__ __forceinline__ void mma16816(float* c, const uint32_t* a,
                                         uint32_t b0, uint32_t b1) {
    asm volatile(
        "mma.sync.aligned.m16n8k16.row.col.f32.bf16.bf16.f32 "
        "{%0,%1,%2,%3}, {%4,%5,%6,%7}, {%8,%9}, {%0,%1,%2,%3};"
        : "+f"(c[0]), "+f"(c[1]), "+f"(c[2]), "+f"(c[3])
        : "r"(a[0]), "r"(a[1]), "r"(a[2]), "r"(a[3]), "r"(b0), "r"(b1));
}

__device__ __forceinline__ uint32_t packbf(float a, float b) {
    __nv_bfloat162 t = __floats2bfloat162_rn(a, b);
    return *reinterpret_cast<uint32_t*>(&t);
}

__device__ __forceinline__ void split_pack(float4 v, uint2& hi, uint2& lo) {
    __nv_bfloat16 hx = __float2bfloat16(v.x);
    __nv_bfloat16 hy = __float2bfloat16(v.y);
    __nv_bfloat16 hz = __float2bfloat16(v.z);
    __nv_bfloat16 hw = __float2bfloat16(v.w);
    hi.x = packbf(v.x, v.y);
    hi.y = packbf(v.z, v.w);
    lo.x = packbf(v.x - __bfloat162float(hx), v.y - __bfloat162float(hy));
    lo.y = packbf(v.z - __bfloat162float(hz), v.w - __bfloat162float(hw));
}

__device__ __forceinline__ void store_split(uint16_t* Dh, uint16_t* Dl,
                                            size_t idx, float val) {
    __nv_bfloat16 h = __float2bfloat16(val);
    *(__nv_bfloat16*)&Dh[idx] = h;
    *(__nv_bfloat16*)&Dl[idx] = __float2bfloat16(val - __bfloat162float(h));
}

// ---------------------------------------------------------------------------
__global__ __launch_bounds__(256) void presplit_kernel(
    const float4* __restrict__ W, uint16_t* __restrict__ Wh,
    uint16_t* __restrict__ Wl)
{
#pragma unroll
    for (int u = 0; u < 4; ++u) {
        int i = (blockIdx.x * 4 + u) * 256 + threadIdx.x;
        float4 v = W[i];
        uint2 hi, lo;
        split_pack(v, hi, lo);
        ((uint2*)Wh)[i] = hi;
        ((uint2*)Wl)[i] = lo;
    }
}

// ---------------------------------------------------------------------------
template <int ROWS, int BK, int PADX>
__device__ __forceinline__ void load_bf16_tile(
    uint16_t* dh, uint16_t* dl, const uint16_t* sh, const uint16_t* sl,
    int ld, int k0, int tid)
{
    constexpr int U4 = BK / 8;
    constexpr int IT = ROWS * U4 / 256;
#pragma unroll
    for (int i = 0; i < IT; ++i) {
        int f = tid + i * 256;
        int r = f / U4, c = (f % U4) * 8;
        *(uint4*)&dh[r * PADX + c] = *(const uint4*)(sh + (size_t)r * ld + k0 + c);
        *(uint4*)&dl[r * PADX + c] = *(const uint4*)(sl + (size_t)r * ld + k0 + c);
    }
}

// ---------------------------------------------------------------------------
// 3xBF16 mma.sync NT-GEMM.  STAGE:
//  0: proj Q/K : A f32 (split in-kernel) x presplit W -> split-head bf16
//  1: proj V   : same -> transposed bf16 [B,H,D,S]
//  2: scores   : bf16 qh @ kh^T; epilogue: exp(logit/8) -> attn + row partials
//  3: ctx      : exp-probs f32 * inv (normalize, write back, split) @ vt^T
//  4: fc       : bf16 ctx @ fcw^T + b, ReLU -> f32 out
// ---------------------------------------------------------------------------
template <int STAGE>
__global__ __launch_bounds__(256, 2) void mma_gemm(
    const uint16_t* __restrict__ Ah, const uint16_t* __restrict__ Al,
    const float*    __restrict__ Af,
    const uint16_t* __restrict__ Bh, const uint16_t* __restrict__ Bl,
    const float* __restrict__ bias,
    float* __restrict__ Df, uint16_t* __restrict__ Dh, uint16_t* __restrict__ Dl,
    float* __restrict__ aux)
{
    constexpr int NT   = (STAGE == 3) ? 64 : 128;
    constexpr int BK   = (STAGE == 2) ? 64 : 32;
    constexpr int KTOT = (STAGE == 2) ? 64 : ((STAGE == 3) ? 2048 : 1024);
    constexpr int KC   = KTOT / BK;
    constexpr int LDA  = (STAGE == 2) ? 64 : ((STAGE == 3) ? 2048 : 1024);
    constexpr int LDB  = (STAGE == 2) ? 64 : ((STAGE == 3) ? 2048 : 1024);
    constexpr int PADX = (STAGE == 2) ? 72 : 40;
    constexpr int KSL  = BK / 16;
    constexpr int WN     = NT / 2;
    constexpr int NPAIRS = WN / 16;
    constexpr int NTILES = 2 * NPAIRS;
    constexpr bool A_F32 = (STAGE <= 1) || (STAGE == 3);

    extern __shared__ __align__(16) uint16_t dsm[];
    uint16_t* sA_h = dsm;
    uint16_t* sA_l = sA_h + 128 * PADX;
    uint16_t* sB_h = sA_l + 128 * PADX;
    uint16_t* sB_l = sB_h + NT * PADX;

    __shared__ float s_ps[128][2];   // stage 2: per-row partial sums (per warp_n)
    __shared__ float s_inv[128];     // stage 3: per-row 1/sum

    const int tid  = threadIdx.x;
    const int wid  = tid >> 5;
    const int lane = tid & 31;
    const int warp_m = wid >> 1;
    const int warp_n = wid & 1;

    const int m0 = blockIdx.y * 128;
    const int n0 = blockIdx.x * NT;
    const int bh = blockIdx.z;

    if constexpr (STAGE == 2) {
        size_t ao = (size_t)bh * SS * DD + (size_t)m0 * LDA;
        size_t bo = (size_t)bh * SS * DD + (size_t)n0 * LDB;
        Ah += ao; Al += ao; Bh += bo; Bl += bo;
    } else if constexpr (STAGE == 3) {
        size_t ao = (size_t)bh * SS * SS + (size_t)m0 * LDA;
        Af += ao; Df += ao;            // Df aliases attn for normalized writeback
        size_t bo = (size_t)bh * DD * SS;
        Bh += bo; Bl += bo;
    } else if constexpr (A_F32) {
        Af += (size_t)m0 * LDA;
        size_t bo = (size_t)n0 * LDB;
        Bh += bo; Bl += bo;
    } else {
        size_t ao = (size_t)m0 * LDA;
        size_t bo = (size_t)n0 * LDB;
        Ah += ao; Al += ao; Bh += bo; Bl += bo;
    }

    if constexpr (STAGE == 3) {
        // fused rowinv: sum this row's 16 partials, reciprocal
        if (tid < 128) {
            const float4* p = (const float4*)(aux + ((size_t)bh * SS + m0 + tid) * 16);
            float4 a = p[0], b = p[1], c = p[2], d = p[3];
            float s = ((a.x + a.y) + (a.z + a.w)) + ((b.x + b.y) + (b.z + b.w))
                    + ((c.x + c.y) + (c.z + c.w)) + ((d.x + d.y) + (d.z + d.w));
            s_inv[tid] = 1.0f / s;
        }
        __syncthreads();
    }

    float acc[2][NTILES][4];
#pragma unroll
    for (int mt = 0; mt < 2; ++mt)
#pragma unroll
        for (int nt = 0; nt < NTILES; ++nt)
#pragma unroll
            for (int i = 0; i < 4; ++i) acc[mt][nt][i] = 0.f;

    for (int ch = 0; ch < KC; ++ch) {
        const int k0 = ch * BK;
        if (ch) __syncthreads();

        if constexpr (A_F32) {
#pragma unroll
            for (int i = 0; i < 4; ++i) {
                int f = tid + i * 256;
                int r = f >> 3, c = (f & 7) << 2;
                float4 v;
                if constexpr (STAGE == 3) {
                    v = __ldcs((const float4*)(Af + (size_t)r * LDA + k0 + c));
                    float iv = s_inv[r];
                    v.x *= iv; v.y *= iv; v.z *= iv; v.w *= iv;
                    __stcs((float4*)(Df + (size_t)r * LDA + k0 + c), v); // normalized attn
                } else {
                    v = *(const float4*)(Af + (size_t)r * LDA + k0 + c);
                }
                uint2 hi, lo;
                split_pack(v, hi, lo);
                *(uint2*)&sA_h[r * PADX + c] = hi;
                *(uint2*)&sA_l[r * PADX + c] = lo;
            }
        } else {
            load_bf16_tile<128, BK, PADX>(sA_h, sA_l, Ah, Al, LDA, k0, tid);
        }
        load_bf16_tile<NT, BK, PADX>(sB_h, sB_l, Bh, Bl, LDB, k0, tid);
        __syncthreads();

#pragma unroll
        for (int ks = 0; ks < KSL; ++ks) {
            const int kcol = ks * 16 + (lane >> 4) * 8;
            uint32_t ah[2][4], al[2][4];
#pragma unroll
            for (int mt = 0; mt < 2; ++mt) {
                int row = warp_m * 32 + mt * 16 + (lane & 15);
                ldsm4(ah[mt], smem_u32(&sA_h[row * PADX + kcol]));
                ldsm4(al[mt], smem_u32(&sA_l[row * PADX + kcol]));
            }
            uint32_t bhf[NPAIRS][4], blf[NPAIRS][4];
#pragma unroll
            for (int np = 0; np < NPAIRS; ++np) {
                int nrow = warp_n * WN + np * 16 + (lane & 15);
                ldsm4(bhf[np], smem_u32(&sB_h[nrow * PADX + kcol]));
                ldsm4(blf[np], smem_u32(&sB_l[nrow * PADX + kcol]));
            }
#pragma unroll
            for (int mt = 0; mt < 2; ++mt)
#pragma unroll
                for (int np = 0; np < NPAIRS; ++np)
#pragma unroll
                    for (int sub = 0; sub < 2; ++sub)
                        mma16816(acc[mt][np * 2 + sub], ah[mt],
                                 bhf[np][sub], bhf[np][sub + 2]);
#pragma unroll
            for (int mt = 0; mt < 2; ++mt)
#pragma unroll
                for (int np = 0; np < NPAIRS; ++np)
#pragma unroll
                    for (int sub = 0; sub < 2; ++sub)
                        mma16816(acc[mt][np * 2 + sub], ah[mt],
                                 blf[np][sub], blf[np][sub + 2]);
#pragma unroll
            for (int mt = 0; mt < 2; ++mt)
#pragma unroll
                for (int np = 0; np < NPAIRS; ++np)
#pragma unroll
                    for (int sub = 0; sub < 2; ++sub)
                        mma16816(acc[mt][np * 2 + sub], al[mt],
                                 bhf[np][sub], bhf[np][sub + 2]);
        }
    }

    // ---- epilogue ----
    const int g = lane >> 2;
    const int j = (lane & 3) << 1;
    const int m_base = m0 + warp_m * 32;
    const int n_base = n0 + warp_n * WN;

    if constexpr (STAGE == 2) {
        // exp, write attn (vectorized streaming), accumulate row partial sums
        float rsum[2][2] = {{0.f, 0.f}, {0.f, 0.f}};
#pragma unroll
        for (int mt = 0; mt < 2; ++mt) {
#pragma unroll
            for (int nt = 0; nt < NTILES; ++nt) {
#pragma unroll
                for (int h = 0; h < 2; ++h) {
                    int row = m_base + mt * 16 + g + h * 8;
                    int col = n_base + nt * 8 + j;
                    float e0 = __expf(acc[mt][nt][h * 2 + 0] * 0.125f);
                    float e1 = __expf(acc[mt][nt][h * 2 + 1] * 0.125f);
                    __stcs((float2*)(Df + ((size_t)bh * SS + row) * SS + col),
                           make_float2(e0, e1));
                    rsum[mt][h] += e0 + e1;
                }
            }
        }
#pragma unroll
        for (int mt = 0; mt < 2; ++mt) {
#pragma unroll
            for (int h = 0; h < 2; ++h) {
                float r = rsum[mt][h];
                r += __shfl_xor_sync(0xffffffffu, r, 1);
                r += __shfl_xor_sync(0xffffffffu, r, 2);
                if ((lane & 3) == 0) {
                    int lrow = warp_m * 32 + mt * 16 + g + h * 8;
                    s_ps[lrow][warp_n] = r;
                }
            }
        }
        __syncthreads();
        if (tid < 128) {
            aux[((size_t)bh * SS + m0 + tid) * 16 + blockIdx.x] =
                s_ps[tid][0] + s_ps[tid][1];
        }
    } else {
#pragma unroll
        for (int mt = 0; mt < 2; ++mt) {
#pragma unroll
            for (int nt = 0; nt < NTILES; ++nt) {
#pragma unroll
                for (int e = 0; e < 4; ++e) {
                    int row = m_base + mt * 16 + g + (e >> 1) * 8;
                    int col = n_base + nt * 8 + j + (e & 1);
                    float val = acc[mt][nt][e];
                    if constexpr (STAGE == 0) {
                        val += bias[col];
                        int b = row >> 11, s = row & 2047, h = col >> 6, d = col & 63;
                        store_split(Dh, Dl, (((size_t)b * HH + h) * SS + s) * DD + d, val);
                    } else if constexpr (STAGE == 1) {
                        val += bias[col];
                        int b = row >> 11, s = row & 2047, h = col >> 6, d = col & 63;
                        store_split(Dh, Dl, (((size_t)b * HH + h) * DD + d) * SS + s, val);
                    } else if constexpr (STAGE == 3) {
                        int b = bh >> 4, h = bh & 15;
                        store_split(Dh, Dl,
                                    ((size_t)b * SS + row) * FF + h * DD + col, val);
                    } else {
                        val += bias[col];
                        Df[(size_t)row * FF + col] = fmaxf(val, 0.f);
                    }
                }
            }
        }
    }
}

// ---------------------------------------------------------------------------
extern "C" void kernel_launch(void* const* d_in, const int* in_sizes, int n_in,
                              void* d_out, int out_size)
{
    const float* q    = (const float*)d_in[0];
    const float* k    = (const float*)d_in[1];
    const float* v    = (const float*)d_in[2];
    const float* wq_w = (const float*)d_in[3];
    const float* wq_b = (const float*)d_in[4];
    const float* wk_w = (const float*)d_in[5];
    const float* wk_b = (const float*)d_in[6];
    const float* wv_w = (const float*)d_in[7];
    const float* wv_b = (const float*)d_in[8];
    const float* fc_w = (const float*)d_in[9];
    const float* fc_b = (const float*)d_in[10];

    float* out  = (float*)d_out;
    float* attn = out + (size_t)BB * SS * FF;

    uint16_t *wq_h, *wq_l, *wk_h, *wk_l, *wv_h, *wv_l, *fcw_h, *fcw_l;
    uint16_t *qh_h, *qh_l, *kh_h, *kh_l, *vt_h, *vt_l, *ctx_h, *ctx_l;
    float *part;
    cudaGetSymbolAddress((void**)&wq_h, g_wq_h); cudaGetSymbolAddress((void**)&wq_l, g_wq_l);
    cudaGetSymbolAddress((void**)&wk_h, g_wk_h); cudaGetSymbolAddress((void**)&wk_l, g_wk_l);
    cudaGetSymbolAddress((void**)&wv_h, g_wv_h); cudaGetSymbolAddress((void**)&wv_l, g_wv_l);
    cudaGetSymbolAddress((void**)&fcw_h, g_fcw_h); cudaGetSymbolAddress((void**)&fcw_l, g_fcw_l);
    cudaGetSymbolAddress((void**)&qh_h, g_qh_h); cudaGetSymbolAddress((void**)&qh_l, g_qh_l);
    cudaGetSymbolAddress((void**)&kh_h, g_kh_h); cudaGetSymbolAddress((void**)&kh_l, g_kh_l);
    cudaGetSymbolAddress((void**)&vt_h, g_vt_h); cudaGetSymbolAddress((void**)&vt_l, g_vt_l);
    cudaGetSymbolAddress((void**)&ctx_h, g_ctx_h); cudaGetSymbolAddress((void**)&ctx_l, g_ctx_l);
    cudaGetSymbolAddress((void**)&part, g_part);

    const int SM_PROJ = (128 * 40 * 2 + 128 * 40 * 2) * 2;  // 40960
    const int SM_SCOR = (128 * 72 * 2 + 128 * 72 * 2) * 2;  // 73728
    const int SM_CTX  = (128 * 40 * 2 + 64 * 40 * 2) * 2;   // 30720

    cudaFuncSetAttribute(mma_gemm<0>, cudaFuncAttributeMaxDynamicSharedMemorySize, SM_PROJ);
    cudaFuncSetAttribute(mma_gemm<1>, cudaFuncAttributeMaxDynamicSharedMemorySize, SM_PROJ);
    cudaFuncSetAttribute(mma_gemm<2>, cudaFuncAttributeMaxDynamicSharedMemorySize, SM_SCOR);
    cudaFuncSetAttribute(mma_gemm<3>, cudaFuncAttributeMaxDynamicSharedMemorySize, SM_CTX);
    cudaFuncSetAttribute(mma_gemm<4>, cudaFuncAttributeMaxDynamicSharedMemorySize, SM_PROJ);

    presplit_kernel<<<256, 256>>>((const float4*)wq_w, wq_h, wq_l);
    presplit_kernel<<<256, 256>>>((const float4*)wk_w, wk_h, wk_l);
    presplit_kernel<<<256, 256>>>((const float4*)wv_w, wv_h, wv_l);
    presplit_kernel<<<256, 256>>>((const float4*)fc_w, fcw_h, fcw_l);

    dim3 gProj(FF / 128, (BB * SS) / 128);     // (8, 64)
    mma_gemm<0><<<gProj, 256, SM_PROJ>>>(nullptr, nullptr, q, wq_h, wq_l, wq_b,
                                         nullptr, qh_h, qh_l, nullptr);
    mma_gemm<0><<<gProj, 256, SM_PROJ>>>(nullptr, nullptr, k, wk_h, wk_l, wk_b,
                                         nullptr, kh_h, kh_l, nullptr);
    mma_gemm<1><<<gProj, 256, SM_PROJ>>>(nullptr, nullptr, v, wv_h, wv_l, wv_b,
                                         nullptr, vt_h, vt_l, nullptr);

    dim3 gS(SS / 128, SS / 128, BB * HH);      // (16, 16, 64)
    mma_gemm<2><<<gS, 256, SM_SCOR>>>(qh_h, qh_l, nullptr, kh_h, kh_l, nullptr,
                                      attn, nullptr, nullptr, part);

    dim3 gC(1, SS / 128, BB * HH);             // (1, 16, 64)
    mma_gemm<3><<<gC, 256, SM_CTX>>>(nullptr, nullptr, attn, vt_h, vt_l, nullptr,
                                     attn, ctx_h, ctx_l, part);

    mma_gemm<4><<<gProj, 256, SM_PROJ>>>(ctx_h, ctx_l, nullptr, fcw_h, fcw_l, fc_b,
                                         out, nullptr, nullptr, nullptr);
}

// round 17
// speedup vs baseline: 1.1848x; 1.1848x over previous
#include <cuda_runtime.h>
#include <cuda_bf16.h>
#include <cstdint>

#define BB 4
#define SS 2048
#define FF 1024
#define HH 16
#define DD 64

// ---------------------------------------------------------------------------
// Scratch (allocation-free requirement -> __device__ globals)
// ---------------------------------------------------------------------------
__device__ uint16_t g_wq_h[1048576], g_wq_l[1048576];
__device__ uint16_t g_wk_h[1048576], g_wk_l[1048576];
__device__ uint16_t g_wv_h[1048576], g_wv_l[1048576];
__device__ uint16_t g_fcw_h[1048576], g_fcw_l[1048576];
__device__ uint16_t g_qh_h[8388608], g_qh_l[8388608];   // [B,H,S,D]
__device__ uint16_t g_kh_h[8388608], g_kh_l[8388608];   // [B,H,S,D]
__device__ uint16_t g_vt_h[8388608], g_vt_l[8388608];   // [B,H,D,S]
__device__ uint16_t g_ctx_h[8388608], g_ctx_l[8388608]; // [B,S,F]
__device__ float    g_part[BB*HH*SS*16];                // per-(row, ntile) exp sums

// ---------------------------------------------------------------------------
__device__ __forceinline__ uint32_t smem_u32(const void* p) {
    uint32_t a;
    asm("{ .reg .u64 t; cvta.to.shared.u64 t, %1; cvt.u32.u64 %0, t; }"
        : "=r"(a) : "l"(p));
    return a;
}

__device__ __forceinline__ void ldsm4(uint32_t* r, uint32_t addr) {
    asm volatile("ldmatrix.sync.aligned.m8n8.x4.shared.b16 {%0,%1,%2,%3}, [%4];"
                 : "=r"(r[0]), "=r"(r[1]), "=r"(r[2]), "=r"(r[3]) : "r"(addr));
}

__device__ __forceinline__ void mma16816(float* c, const uint32_t* a,
                                         uint32_t b0, uint32_t b1) {
    asm volatile(
        "mma.sync.aligned.m16n8k16.row.col.f32.bf16.bf16.f32 "
        "{%0,%1,%2,%3}, {%4,%5,%6,%7}, {%8,%9}, {%0,%1,%2,%3};"
        : "+f"(c[0]), "+f"(c[1]), "+f"(c[2]), "+f"(c[3])
        : "r"(a[0]), "r"(a[1]), "r"(a[2]), "r"(a[3]), "r"(b0), "r"(b1));
}

__device__ __forceinline__ uint32_t packbf(float a, float b) {
    __nv_bfloat162 t = __floats2bfloat162_rn(a, b);
    return *reinterpret_cast<uint32_t*>(&t);
}

__device__ __forceinline__ void split_pack(float4 v, uint2& hi, uint2& lo) {
    __nv_bfloat16 hx = __float2bfloat16(v.x);
    __nv_bfloat16 hy = __float2bfloat16(v.y);
    __nv_bfloat16 hz = __float2bfloat16(v.z);
    __nv_bfloat16 hw = __float2bfloat16(v.w);
    hi.x = packbf(v.x, v.y);
    hi.y = packbf(v.z, v.w);
    lo.x = packbf(v.x - __bfloat162float(hx), v.y - __bfloat162float(hy));
    lo.y = packbf(v.z - __bfloat162float(hz), v.w - __bfloat162float(hw));
}

__device__ __forceinline__ void store_split(uint16_t* Dh, uint16_t* Dl,
                                            size_t idx, float val) {
    __nv_bfloat16 h = __float2bfloat16(val);
    *(__nv_bfloat16*)&Dh[idx] = h;
    *(__nv_bfloat16*)&Dl[idx] = __float2bfloat16(val - __bfloat162float(h));
}

// ---------------------------------------------------------------------------
__global__ __launch_bounds__(256) void presplit_kernel(
    const float4* __restrict__ W, uint16_t* __restrict__ Wh,
    uint16_t* __restrict__ Wl)
{
#pragma unroll
    for (int u = 0; u < 4; ++u) {
        int i = (blockIdx.x * 4 + u) * 256 + threadIdx.x;
        float4 v = W[i];
        uint2 hi, lo;
        split_pack(v, hi, lo);
        ((uint2*)Wh)[i] = hi;
        ((uint2*)Wl)[i] = lo;
    }
}

// ---------------------------------------------------------------------------
template <int ROWS, int BK, int PADX>
__device__ __forceinline__ void load_bf16_tile(
    uint16_t* dh, uint16_t* dl, const uint16_t* sh, const uint16_t* sl,
    int ld, int k0, int tid)
{
    constexpr int U4 = BK / 8;
    constexpr int IT = ROWS * U4 / 256;
#pragma unroll
    for (int i = 0; i < IT; ++i) {
        int f = tid + i * 256;
        int r = f / U4, c = (f % U4) * 8;
        *(uint4*)&dh[r * PADX + c] = *(const uint4*)(sh + (size_t)r * ld + k0 + c);
        *(uint4*)&dl[r * PADX + c] = *(const uint4*)(sl + (size_t)r * ld + k0 + c);
    }
}

// ---------------------------------------------------------------------------
// 3xBF16 mma.sync NT-GEMM.  STAGE:
//  0: proj Q/K : A f32 (split in-kernel) x presplit W -> split-head bf16
//  1: proj V   : same -> transposed bf16 [B,H,D,S]
//  2: scores   : bf16 qh @ kh^T; epilogue: exp(logit/8) -> attn + row partials
//  3: ctx      : exp-probs f32 * inv (normalize, write back, split) @ vt^T
//  4: fc       : bf16 ctx @ fcw^T + b, ReLU -> f32 out
// ---------------------------------------------------------------------------
template <int STAGE>
__global__ __launch_bounds__(256, 2) void mma_gemm(
    const uint16_t* __restrict__ Ah, const uint16_t* __restrict__ Al,
    const float*    __restrict__ Af,
    const uint16_t* __restrict__ Bh, const uint16_t* __restrict__ Bl,
    const float* __restrict__ bias,
    float* __restrict__ Df, uint16_t* __restrict__ Dh, uint16_t* __restrict__ Dl,
    float* __restrict__ aux)
{
    constexpr int NT   = (STAGE == 3) ? 64 : 128;
    constexpr int BK   = (STAGE == 2) ? 64 : 32;
    constexpr int KTOT = (STAGE == 2) ? 64 : ((STAGE == 3) ? 2048 : 1024);
    constexpr int KC   = KTOT / BK;
    constexpr int LDA  = (STAGE == 2) ? 64 : ((STAGE == 3) ? 2048 : 1024);
    constexpr int LDB  = (STAGE == 2) ? 64 : ((STAGE == 3) ? 2048 : 1024);
    constexpr int PADX = (STAGE == 2) ? 72 : 40;
    constexpr int KSL  = BK / 16;
    constexpr int WN     = NT / 2;
    constexpr int NPAIRS = WN / 16;
    constexpr int NTILES = 2 * NPAIRS;
    constexpr bool A_F32 = (STAGE <= 1) || (STAGE == 3);

    extern __shared__ __align__(16) uint16_t dsm[];
    uint16_t* sA_h = dsm;
    uint16_t* sA_l = sA_h + 128 * PADX;
    uint16_t* sB_h = sA_l + 128 * PADX;
    uint16_t* sB_l = sB_h + NT * PADX;

    __shared__ float s_ps[128][2];   // stage 2: per-row partial sums (per warp_n)
    __shared__ float s_inv[128];     // stage 3: per-row 1/sum

    const int tid  = threadIdx.x;
    const int wid  = tid >> 5;
    const int lane = tid & 31;
    const int warp_m = wid >> 1;
    const int warp_n = wid & 1;

    const int m0 = blockIdx.y * 128;
    const int n0 = blockIdx.x * NT;
    const int bh = blockIdx.z;

    if constexpr (STAGE == 2) {
        size_t ao = (size_t)bh * SS * DD + (size_t)m0 * LDA;
        size_t bo = (size_t)bh * SS * DD + (size_t)n0 * LDB;
        Ah += ao; Al += ao; Bh += bo; Bl += bo;
    } else if constexpr (STAGE == 3) {
        size_t ao = (size_t)bh * SS * SS + (size_t)m0 * LDA;
        Af += ao; Df += ao;            // Df aliases attn for normalized writeback
        size_t bo = (size_t)bh * DD * SS;
        Bh += bo; Bl += bo;
    } else if constexpr (A_F32) {
        Af += (size_t)m0 * LDA;
        size_t bo = (size_t)n0 * LDB;
        Bh += bo; Bl += bo;
    } else {
        size_t ao = (size_t)m0 * LDA;
        size_t bo = (size_t)n0 * LDB;
        Ah += ao; Al += ao; Bh += bo; Bl += bo;
    }

    if constexpr (STAGE == 3) {
        // fused rowinv: sum this row's 16 partials, reciprocal
        if (tid < 128) {
            const float4* p = (const float4*)(aux + ((size_t)bh * SS + m0 + tid) * 16);
            float4 a = p[0], b = p[1], c = p[2], d = p[3];
            float s = ((a.x + a.y) + (a.z + a.w)) + ((b.x + b.y) + (b.z + b.w))
                    + ((c.x + c.y) + (c.z + c.w)) + ((d.x + d.y) + (d.z + d.w));
            s_inv[tid] = 1.0f / s;
        }
        __syncthreads();
    }

    float acc[2][NTILES][4];
#pragma unroll
    for (int mt = 0; mt < 2; ++mt)
#pragma unroll
        for (int nt = 0; nt < NTILES; ++nt)
#pragma unroll
            for (int i = 0; i < 4; ++i) acc[mt][nt][i] = 0.f;

    for (int ch = 0; ch < KC; ++ch) {
        const int k0 = ch * BK;
        if (ch) __syncthreads();

        if constexpr (A_F32) {
#pragma unroll
            for (int i = 0; i < 4; ++i) {
                int f = tid + i * 256;
                int r = f >> 3, c = (f & 7) << 2;
                float4 v = *(const float4*)(Af + (size_t)r * LDA + k0 + c);
                if constexpr (STAGE == 3) {
                    float iv = s_inv[r];
                    v.x *= iv; v.y *= iv; v.z *= iv; v.w *= iv;
                    *(float4*)(Df + (size_t)r * LDA + k0 + c) = v;  // normalized attn
                }
                uint2 hi, lo;
                split_pack(v, hi, lo);
                *(uint2*)&sA_h[r * PADX + c] = hi;
                *(uint2*)&sA_l[r * PADX + c] = lo;
            }
        } else {
            load_bf16_tile<128, BK, PADX>(sA_h, sA_l, Ah, Al, LDA, k0, tid);
        }
        load_bf16_tile<NT, BK, PADX>(sB_h, sB_l, Bh, Bl, LDB, k0, tid);
        __syncthreads();

#pragma unroll
        for (int ks = 0; ks < KSL; ++ks) {
            const int kcol = ks * 16 + (lane >> 4) * 8;
            uint32_t ah[2][4], al[2][4];
#pragma unroll
            for (int mt = 0; mt < 2; ++mt) {
                int row = warp_m * 32 + mt * 16 + (lane & 15);
                ldsm4(ah[mt], smem_u32(&sA_h[row * PADX + kcol]));
                ldsm4(al[mt], smem_u32(&sA_l[row * PADX + kcol]));
            }
            uint32_t bhf[NPAIRS][4], blf[NPAIRS][4];
#pragma unroll
            for (int np = 0; np < NPAIRS; ++np) {
                int nrow = warp_n * WN + np * 16 + (lane & 15);
                ldsm4(bhf[np], smem_u32(&sB_h[nrow * PADX + kcol]));
                ldsm4(blf[np], smem_u32(&sB_l[nrow * PADX + kcol]));
            }
#pragma unroll
            for (int mt = 0; mt < 2; ++mt)
#pragma unroll
                for (int np = 0; np < NPAIRS; ++np)
#pragma unroll
                    for (int sub = 0; sub < 2; ++sub)
                        mma16816(acc[mt][np * 2 + sub], ah[mt],
                                 bhf[np][sub], bhf[np][sub + 2]);
#pragma unroll
            for (int mt = 0; mt < 2; ++mt)
#pragma unroll
                for (int np = 0; np < NPAIRS; ++np)
#pragma unroll
                    for (int sub = 0; sub < 2; ++sub)
                        mma16816(acc[mt][np * 2 + sub], ah[mt],
                                 blf[np][sub], blf[np][sub + 2]);
#pragma unroll
            for (int mt = 0; mt < 2; ++mt)
#pragma unroll
                for (int np = 0; np < NPAIRS; ++np)
#pragma unroll
                    for (int sub = 0; sub < 2; ++sub)
                        mma16816(acc[mt][np * 2 + sub], al[mt],
                                 bhf[np][sub], bhf[np][sub + 2]);
        }
    }

    // ---- epilogue ----
    const int g = lane >> 2;
    const int j = (lane & 3) << 1;
    const int m_base = m0 + warp_m * 32;
    const int n_base = n0 + warp_n * WN;

    if constexpr (STAGE == 2) {
        // exp, write attn (plain vectorized), accumulate row partial sums
        float rsum[2][2] = {{0.f, 0.f}, {0.f, 0.f}};
#pragma unroll
        for (int mt = 0; mt < 2; ++mt) {
#pragma unroll
            for (int nt = 0; nt < NTILES; ++nt) {
#pragma unroll
                for (int h = 0; h < 2; ++h) {
                    int row = m_base + mt * 16 + g + h * 8;
                    int col = n_base + nt * 8 + j;
                    float e0 = __expf(acc[mt][nt][h * 2 + 0] * 0.125f);
                    float e1 = __expf(acc[mt][nt][h * 2 + 1] * 0.125f);
                    *(float2*)(Df + ((size_t)bh * SS + row) * SS + col) =
                        make_float2(e0, e1);
                    rsum[mt][h] += e0 + e1;
                }
            }
        }
#pragma unroll
        for (int mt = 0; mt < 2; ++mt) {
#pragma unroll
            for (int h = 0; h < 2; ++h) {
                float r = rsum[mt][h];
                r += __shfl_xor_sync(0xffffffffu, r, 1);
                r += __shfl_xor_sync(0xffffffffu, r, 2);
                if ((lane & 3) == 0) {
                    int lrow = warp_m * 32 + mt * 16 + g + h * 8;
                    s_ps[lrow][warp_n] = r;
                }
            }
        }
        __syncthreads();
        if (tid < 128) {
            aux[((size_t)bh * SS + m0 + tid) * 16 + blockIdx.x] =
                s_ps[tid][0] + s_ps[tid][1];
        }
    } else {
#pragma unroll
        for (int mt = 0; mt < 2; ++mt) {
#pragma unroll
            for (int nt = 0; nt < NTILES; ++nt) {
#pragma unroll
                for (int e = 0; e < 4; ++e) {
                    int row = m_base + mt * 16 + g + (e >> 1) * 8;
                    int col = n_base + nt * 8 + j + (e & 1);
                    float val = acc[mt][nt][e];
                    if constexpr (STAGE == 0) {
                        val += bias[col];
                        int b = row >> 11, s = row & 2047, h = col >> 6, d = col & 63;
                        store_split(Dh, Dl, (((size_t)b * HH + h) * SS + s) * DD + d, val);
                    } else if constexpr (STAGE == 1) {
                        val += bias[col];
                        int b = row >> 11, s = row & 2047, h = col >> 6, d = col & 63;
                        store_split(Dh, Dl, (((size_t)b * HH + h) * DD + d) * SS + s, val);
                    } else if constexpr (STAGE == 3) {
                        int b = bh >> 4, h = bh & 15;
                        store_split(Dh, Dl,
                                    ((size_t)b * SS + row) * FF + h * DD + col, val);
                    } else {
                        val += bias[col];
                        Df[(size_t)row * FF + col] = fmaxf(val, 0.f);
                    }
                }
            }
        }
    }
}

// ---------------------------------------------------------------------------
extern "C" void kernel_launch(void* const* d_in, const int* in_sizes, int n_in,
                              void* d_out, int out_size)
{
    const float* q    = (const float*)d_in[0];
    const float* k    = (const float*)d_in[1];
    const float* v    = (const float*)d_in[2];
    const float* wq_w = (const float*)d_in[3];
    const float* wq_b = (const float*)d_in[4];
    const float* wk_w = (const float*)d_in[5];
    const float* wk_b = (const float*)d_in[6];
    const float* wv_w = (const float*)d_in[7];
    const float* wv_b = (const float*)d_in[8];
    const float* fc_w = (const float*)d_in[9];
    const float* fc_b = (const float*)d_in[10];

    float* out  = (float*)d_out;
    float* attn = out + (size_t)BB * SS * FF;

    uint16_t *wq_h, *wq_l, *wk_h, *wk_l, *wv_h, *wv_l, *fcw_h, *fcw_l;
    uint16_t *qh_h, *qh_l, *kh_h, *kh_l, *vt_h, *vt_l, *ctx_h, *ctx_l;
    float *part;
    cudaGetSymbolAddress((void**)&wq_h, g_wq_h); cudaGetSymbolAddress((void**)&wq_l, g_wq_l);
    cudaGetSymbolAddress((void**)&wk_h, g_wk_h); cudaGetSymbolAddress((void**)&wk_l, g_wk_l);
    cudaGetSymbolAddress((void**)&wv_h, g_wv_h); cudaGetSymbolAddress((void**)&wv_l, g_wv_l);
    cudaGetSymbolAddress((void**)&fcw_h, g_fcw_h); cudaGetSymbolAddress((void**)&fcw_l, g_fcw_l);
    cudaGetSymbolAddress((void**)&qh_h, g_qh_h); cudaGetSymbolAddress((void**)&qh_l, g_qh_l);
    cudaGetSymbolAddress((void**)&kh_h, g_kh_h); cudaGetSymbolAddress((void**)&kh_l, g_kh_l);
    cudaGetSymbolAddress((void**)&vt_h, g_vt_h); cudaGetSymbolAddress((void**)&vt_l, g_vt_l);
    cudaGetSymbolAddress((void**)&ctx_h, g_ctx_h); cudaGetSymbolAddress((void**)&ctx_l, g_ctx_l);
    cudaGetSymbolAddress((void**)&part, g_part);

    const int SM_PROJ = (128 * 40 * 2 + 128 * 40 * 2) * 2;  // 40960
    const int SM_SCOR = (128 * 72 * 2 + 128 * 72 * 2) * 2;  // 73728
    const int SM_CTX  = (128 * 40 * 2 + 64 * 40 * 2) * 2;   // 30720

    cudaFuncSetAttribute(mma_gemm<0>, cudaFuncAttributeMaxDynamicSharedMemorySize, SM_PROJ);
    cudaFuncSetAttribute(mma_gemm<1>, cudaFuncAttributeMaxDynamicSharedMemorySize, SM_PROJ);
    cudaFuncSetAttribute(mma_gemm<2>, cudaFuncAttributeMaxDynamicSharedMemorySize, SM_SCOR);
    cudaFuncSetAttribute(mma_gemm<3>, cudaFuncAttributeMaxDynamicSharedMemorySize, SM_CTX);
    cudaFuncSetAttribute(mma_gemm<4>, cudaFuncAttributeMaxDynamicSharedMemorySize, SM_PROJ);

    presplit_kernel<<<256, 256>>>((const float4*)wq_w, wq_h, wq_l);
    presplit_kernel<<<256, 256>>>((const float4*)wk_w, wk_h, wk_l);
    presplit_kernel<<<256, 256>>>((const float4*)wv_w, wv_h, wv_l);
    presplit_kernel<<<256, 256>>>((const float4*)fc_w, fcw_h, fcw_l);

    dim3 gProj(FF / 128, (BB * SS) / 128);     // (8, 64)
    mma_gemm<0><<<gProj, 256, SM_PROJ>>>(nullptr, nullptr, q, wq_h, wq_l, wq_b,
                                         nullptr, qh_h, qh_l, nullptr);
    mma_gemm<0><<<gProj, 256, SM_PROJ>>>(nullptr, nullptr, k, wk_h, wk_l, wk_b,
                                         nullptr, kh_h, kh_l, nullptr);
    mma_gemm<1><<<gProj, 256, SM_PROJ>>>(nullptr, nullptr, v, wv_h, wv_l, wv_b,
                                         nullptr, vt_h, vt_l, nullptr);

    dim3 gS(SS / 128, SS / 128, BB * HH);      // (16, 16, 64)
    mma_gemm<2><<<gS, 256, SM_SCOR>>>(qh_h, qh_l, nullptr, kh_h, kh_l, nullptr,
                                      attn, nullptr, nullptr, part);

    dim3 gC(1, SS / 128, BB * HH);             // (1, 16, 64)
    mma_gemm<3><<<gC, 256, SM_CTX>>>(nullptr, nullptr, attn, vt_h, vt_l, nullptr,
                                     attn, ctx_h, ctx_l, part);

    mma_gemm<4><<<gProj, 256, SM_PROJ>>>(ctx_h, ctx_l, nullptr, fcw_h, fcw_l, fc_b,
                                         out, nullptr, nullptr, nullptr);
}